// round 8
// baseline (speedup 1.0000x reference)
#include <cuda_runtime.h>
#include <cuda_fp16.h>
#include <cstdint>

namespace {

constexpr int Bc = 2, Hc = 12, Sc = 2048, Dc = 64;
constexpr int BM = 128;          // q rows per CTA (16 per warp)
constexpr int BN = 32;           // keys per tile
constexpr int NT = 256;          // 8 warps
constexpr int NTILE = Sc / BN;   // 64
constexpr int NSTAGE = 3;
constexpr int SPLIT = 3;         // key-range splits (wave-quantization fix)
constexpr int PITCHW = 36;       // smem row pitch in words (144 B)
constexpr int WBUF = BN * PITCHW;
constexpr int GBUF = BN * 32;
constexpr float SCALE = 0.125f;
constexpr float LOG2E = 1.44269504f;
// M0 = 0: p = e^s stays fp16-normal (R5 failed on denormal quantization, not rounding)

__constant__ int TS[SPLIT + 1] = {0, 21, 42, 64};   // tile ranges per split

__device__ uint32_t g_mask_bits[(size_t)Bc * Sc * (Sc / 32)];       // 1 MB
__device__ uint32_t g_kv[(size_t)Bc * Hc * NTILE * 2 * GBUF];       // 12.6 MB
__device__ float4   g_po[(size_t)SPLIT * Bc * Hc * Sc * (Dc / 4)];  // 37.7 MB partial O
__device__ float    g_pl[(size_t)SPLIT * Bc * Hc * Sc];             // 0.6 MB partial lsum

// ---- mask pack: 8 ints/thread, shfl-OR byte combine ----
__global__ void __launch_bounds__(256) mask_pack_kernel(const int4* __restrict__ m) {
    size_t i = (size_t)blockIdx.x * 256 + threadIdx.x;   // 8-int chunk id
    int4 a = m[2 * i], c = m[2 * i + 1];
    uint32_t byte =
        (a.x != 0 ? 1u : 0u)  | (a.y != 0 ? 2u : 0u)  | (a.z != 0 ? 4u : 0u)  | (a.w != 0 ? 8u : 0u) |
        (c.x != 0 ? 16u : 0u) | (c.y != 0 ? 32u : 0u) | (c.z != 0 ? 64u : 0u) | (c.w != 0 ? 128u : 0u);
    uint32_t x = byte << (8 * (threadIdx.x & 3));
    x |= __shfl_xor_sync(0xFFFFFFFFu, x, 1);
    x |= __shfl_xor_sync(0xFFFFFFFFu, x, 2);
    if ((threadIdx.x & 3) == 0) g_mask_bits[i >> 2] = x;
}

// ---- helpers ----
__device__ __forceinline__ uint32_t smem_u32(const void* p) {
    uint32_t a;
    asm("{ .reg .u64 t; cvta.to.shared.u64 t, %1; cvt.u32.u64 %0, t; }" : "=r"(a) : "l"(p));
    return a;
}
__device__ __forceinline__ void cp_async16(uint32_t dst, const void* src) {
    asm volatile("cp.async.cg.shared.global [%0], [%1], 16;" :: "r"(dst), "l"(src));
}
#define CP_COMMIT() asm volatile("cp.async.commit_group;" ::: "memory")
#define CP_WAIT1()  asm volatile("cp.async.wait_group 1;" ::: "memory")

__device__ __forceinline__ void mma_f16(float* d, const uint32_t* a, uint32_t b0, uint32_t b1) {
    asm volatile(
        "mma.sync.aligned.m16n8k16.row.col.f32.f16.f16.f32 "
        "{%0,%1,%2,%3},{%4,%5,%6,%7},{%8,%9},{%0,%1,%2,%3};"
        : "+f"(d[0]), "+f"(d[1]), "+f"(d[2]), "+f"(d[3])
        : "r"(a[0]), "r"(a[1]), "r"(a[2]), "r"(a[3]), "r"(b0), "r"(b1));
}
__device__ __forceinline__ void ldsm_x4(uint32_t* r, uint32_t addr) {
    asm volatile("ldmatrix.sync.aligned.m8n8.x4.shared.b16 {%0,%1,%2,%3},[%4];"
                 : "=r"(r[0]), "=r"(r[1]), "=r"(r[2]), "=r"(r[3]) : "r"(addr));
}
__device__ __forceinline__ void ldsm_x4_t(uint32_t* r, uint32_t addr) {
    asm volatile("ldmatrix.sync.aligned.m8n8.x4.trans.shared.b16 {%0,%1,%2,%3},[%4];"
                 : "=r"(r[0]), "=r"(r[1]), "=r"(r[2]), "=r"(r[3]) : "r"(addr));
}
__device__ __forceinline__ uint32_t pack_h2(float a, float b) {
    uint32_t r;
    asm("cvt.rn.f16x2.f32 %0, %1, %2;" : "=r"(r) : "f"(b), "f"(a));
    return r;
}
__device__ __forceinline__ float ex2(float x) {
    float r;
    asm("ex2.approx.f32 %0, %1;" : "=f"(r) : "f"(x));
    return r;
}

// ---- prep: fp32 K/V -> fp16 tile images ----
__global__ void __launch_bounds__(256) prep_kv_kernel(
    const float* __restrict__ K, const float* __restrict__ V)
{
    const int tile = blockIdx.x;
    const int bh = tile / NTILE, kt = tile % NTILE;
    const int k0 = kt * BN;
    const int t = threadIdx.x;
    uint32_t* out = g_kv + (size_t)tile * 2 * GBUF;
    const float4* K4 = reinterpret_cast<const float4*>(K) + (size_t)bh * Sc * 16;
    const float4* V4 = reinterpret_cast<const float4*>(V) + (size_t)bh * Sc * 16;
#pragma unroll
    for (int i = 0; i < 2; i++) {
        int idx = t + i * 256;
        int r = idx >> 4, c4 = idx & 15;
        int p0 = 2 * c4;
        float4 fk = K4[(size_t)(k0 + r) * 16 + c4];
        *reinterpret_cast<uint2*>(&out[0 * GBUF + r * 32 + p0]) =
            make_uint2(pack_h2(fk.x, fk.y), pack_h2(fk.z, fk.w));
        float4 fv = V4[(size_t)(k0 + r) * 16 + c4];
        *reinterpret_cast<uint2*>(&out[1 * GBUF + r * 32 + p0]) =
            make_uint2(pack_h2(fv.x, fv.y), pack_h2(fv.z, fv.w));
    }
}

// ---- main attention kernel (split-K partials) ----
__global__ void __launch_bounds__(NT, 2) attn_mma_kernel(const float* __restrict__ Q)
{
    extern __shared__ uint32_t sTile[];

    const int t = threadIdx.x;
    const int lane = t & 31, w = t >> 5;
    const int qt = lane >> 2, qc = lane & 3;

    const int q0 = blockIdx.x * BM;
    const int h = blockIdx.y;
    const int z = blockIdx.z;
    const int b = z / SPLIT, sp = z - b * SPLIT;
    const size_t bh = (size_t)b * Hc + h;
    const int qi0 = q0 + w * 16 + qt;
    const int qi1 = qi0 + 8;

    const int kt0 = TS[sp], kt1 = TS[sp + 1];

    // Q A-fragments (fp16), scale folded
    uint32_t qa[4][4];
#pragma unroll
    for (int kk = 0; kk < 4; kk++) {
#pragma unroll
        for (int part = 0; part < 4; part++) {
            int row = (part & 1) ? qi1 : qi0;
            int d = kk * 16 + 2 * qc + ((part & 2) ? 8 : 0);
            const float2 f = *reinterpret_cast<const float2*>(Q + ((bh * Sc + row) << 6) + d);
            qa[kk][part] = pack_h2(f.x * SCALE, f.y * SCALE);
        }
    }

    float oacc[8][4];
#pragma unroll
    for (int j = 0; j < 8; j++)
#pragma unroll
        for (int i = 0; i < 4; i++) oacc[j][i] = 0.0f;
    float lsum0 = 0.0f, lsum1 = 0.0f;

    const uint32_t* mrow0 = g_mask_bits + ((size_t)b * Sc + qi0) * (Sc / 32);
    const uint32_t* mrow1 = g_mask_bits + ((size_t)b * Sc + qi1) * (Sc / 32);
    const uint32_t* kvbase = g_kv + bh * NTILE * 2 * GBUF;
    const uint32_t sbase = smem_u32(sTile);

    auto issue_tile = [&](int kt, int stage) {
        const uint32_t* src = kvbase + (size_t)kt * 2 * GBUF;
        uint32_t dstb = sbase + (uint32_t)stage * 2 * WBUF * 4;
#pragma unroll
        for (int i = 0; i < 2; i++) {
            int chunk = t + i * NT;
            int buf = chunk >> 8, within = chunk & 255;
            int r = within >> 3, ws = within & 7;
            cp_async16(dstb + (uint32_t)(buf * WBUF + r * PITCHW + ws * 4) * 4,
                       src + buf * GBUF + within * 4);
        }
        CP_COMMIT();
    };

    issue_tile(kt0, 0);
    issue_tile(kt0 + 1, 1);

    const int krow = ((lane >> 4) << 3) + (lane & 7);
    const int ksel = (lane >> 3) & 1;
    const int vrow = ((lane >> 3) & 1) * 8 + (lane & 7);
    const int jsel = lane >> 4;

    int stage = 0;
    for (int kt = kt0; kt < kt1; kt++) {
        CP_WAIT1();
        __syncthreads();

        const uint32_t* sK = sTile + stage * 2 * WBUF;
        const uint32_t* sV = sK + WBUF;

        // ---- S = (Q*scale).K^T ----
        float sacc[4][4];
#pragma unroll
        for (int j = 0; j < 4; j++)
#pragma unroll
            for (int i = 0; i < 4; i++) sacc[j][i] = 0.0f;

#pragma unroll
        for (int jp = 0; jp < 2; jp++) {
            const int kr = jp * 16 + krow;
#pragma unroll
            for (int kk = 0; kk < 4; kk++) {
                const int woff = kr * PITCHW + kk * 8 + ksel * 4;
                uint32_t bh4[4];
                ldsm_x4(bh4, smem_u32(&sK[woff]));
                mma_f16(sacc[2 * jp],     qa[kk], bh4[0], bh4[1]);
                mma_f16(sacc[2 * jp + 1], qa[kk], bh4[2], bh4[3]);
            }
        }

        // ---- mask + p = 2^(s*log2e) ----
        const uint32_t mw0 = mrow0[kt];
        const uint32_t mw1 = mrow1[kt];

        float p[4][4];
#pragma unroll
        for (int j = 0; j < 4; j++) {
            const int sh = j * 8 + 2 * qc;
            p[j][0] = (mw0 >> sh) & 1       ? ex2(sacc[j][0] * LOG2E) : 0.0f;
            p[j][1] = (mw0 >> (sh + 1)) & 1 ? ex2(sacc[j][1] * LOG2E) : 0.0f;
            p[j][2] = (mw1 >> sh) & 1       ? ex2(sacc[j][2] * LOG2E) : 0.0f;
            p[j][3] = (mw1 >> (sh + 1)) & 1 ? ex2(sacc[j][3] * LOG2E) : 0.0f;
            lsum0 += p[j][0] + p[j][1];
            lsum1 += p[j][2] + p[j][3];
        }

        uint32_t pa[2][4];
#pragma unroll
        for (int kc = 0; kc < 2; kc++) {
            pa[kc][0] = pack_h2(p[2 * kc][0],     p[2 * kc][1]);
            pa[kc][1] = pack_h2(p[2 * kc][2],     p[2 * kc][3]);
            pa[kc][2] = pack_h2(p[2 * kc + 1][0], p[2 * kc + 1][1]);
            pa[kc][3] = pack_h2(p[2 * kc + 1][2], p[2 * kc + 1][3]);
        }

        // ---- O += P.V ----
#pragma unroll
        for (int kc = 0; kc < 2; kc++) {
            const int vr = kc * 16 + vrow;
#pragma unroll
            for (int jp = 0; jp < 4; jp++) {
                const int woff = vr * PITCHW + (2 * jp + jsel) * 4;
                uint32_t vh4[4];
                ldsm_x4_t(vh4, smem_u32(&sV[woff]));
                mma_f16(oacc[2 * jp],     pa[kc], vh4[0], vh4[1]);
                mma_f16(oacc[2 * jp + 1], pa[kc], vh4[2], vh4[3]);
            }
        }

        if (kt + 2 < kt1) issue_tile(kt + 2, (stage + 2 >= NSTAGE) ? stage + 2 - NSTAGE : stage + 2);
        else              CP_COMMIT();
        stage = (stage + 1 == NSTAGE) ? 0 : stage + 1;
    }

    // ---- partial row sums across quad ----
    lsum0 += __shfl_xor_sync(0xFFFFFFFFu, lsum0, 1);
    lsum0 += __shfl_xor_sync(0xFFFFFFFFu, lsum0, 2);
    lsum1 += __shfl_xor_sync(0xFFFFFFFFu, lsum1, 1);
    lsum1 += __shfl_xor_sync(0xFFFFFFFFu, lsum1, 2);

    // ---- write unnormalized partials ----
    const size_t pobase = ((size_t)sp * Bc * Hc + bh) * Sc;
    float* o0 = reinterpret_cast<float*>(g_po) + (pobase + qi0) * Dc + 2 * qc;
    float* o1 = reinterpret_cast<float*>(g_po) + (pobase + qi1) * Dc + 2 * qc;
#pragma unroll
    for (int j = 0; j < 8; j++) {
        *reinterpret_cast<float2*>(o0 + j * 8) = make_float2(oacc[j][0], oacc[j][1]);
        *reinterpret_cast<float2*>(o1 + j * 8) = make_float2(oacc[j][2], oacc[j][3]);
    }
    if (qc == 0) {
        g_pl[pobase + qi0] = lsum0;
        g_pl[pobase + qi1] = lsum1;
    }
}

// ---- reduce: combine split partials, normalize ----
__global__ void __launch_bounds__(256) reduce_kernel(float4* __restrict__ Og) {
    const size_t idx = (size_t)blockIdx.x * 256 + threadIdx.x;  // float4 id
    const size_t row = idx >> 4;                                 // bh*Sc + s row
    const int c4 = (int)(idx & 15);
    constexpr size_t PO_STRIDE = (size_t)Bc * Hc * Sc;           // rows per split

    float4 acc = make_float4(0.f, 0.f, 0.f, 0.f);
    float l = 0.f;
#pragma unroll
    for (int sp = 0; sp < SPLIT; sp++) {
        float4 v = g_po[(sp * PO_STRIDE + row) * 16 + c4];
        acc.x += v.x; acc.y += v.y; acc.z += v.z; acc.w += v.w;
        l += g_pl[sp * PO_STRIDE + row];
    }
    const float inv = 1.0f / l;
    acc.x *= inv; acc.y *= inv; acc.z *= inv; acc.w *= inv;
    Og[idx] = acc;
}

} // namespace

extern "C" void kernel_launch(void* const* d_in, const int* in_sizes, int n_in,
                              void* d_out, int out_size)
{
    const float* Q = (const float*)d_in[0];
    const float* K = (const float*)d_in[1];
    const float* V = (const float*)d_in[2];
    const int*   M = (const int*)d_in[3];
    float*       O = (float*)d_out;

    mask_pack_kernel<<<Bc * Sc * Sc / 8 / 256, 256>>>((const int4*)M);
    prep_kv_kernel<<<Bc * Hc * NTILE, 256>>>(K, V);

    static int smem_set = 0;
    const int smem_bytes = NSTAGE * 2 * WBUF * 4;   // 27648
    if (!smem_set) {
        cudaFuncSetAttribute(attn_mma_kernel, cudaFuncAttributeMaxDynamicSharedMemorySize, smem_bytes);
        smem_set = 1;
    }
    dim3 grid(Sc / BM, Hc, Bc * SPLIT);
    attn_mma_kernel<<<grid, NT, smem_bytes>>>(Q);

    const int out_f4 = Bc * Hc * Sc * (Dc / 4);     // 786432
    reduce_kernel<<<out_f4 / 256, 256>>>((float4*)O);
}

// round 9
// speedup vs baseline: 1.0208x; 1.0208x over previous
#include <cuda_runtime.h>
#include <cuda_fp16.h>
#include <cstdint>

namespace {

constexpr int Bc = 2, Hc = 12, Sc = 2048, Dc = 64;
constexpr int BM = 128;          // q rows per CTA (16 per warp)
constexpr int BN = 32;           // keys per tile
constexpr int NT = 256;          // 8 warps
constexpr int NTILE = Sc / BN;   // 64
constexpr int NSTAGE = 3;
constexpr int PITCHW = 36;       // smem row pitch in words (144 B)
constexpr int WBUF = BN * PITCHW;
constexpr int GBUF = BN * 32;
constexpr float SCALE = 0.125f;
constexpr float LOG2E = 1.44269504f;
// M0 = 0: p = e^s stays fp16-normal (R5 failed on denormal quantization, not rounding)

__device__ uint32_t g_mask_bits[(size_t)Bc * Sc * (Sc / 32)];     // 1 MB
__device__ uint32_t g_kv[(size_t)Bc * Hc * NTILE * 2 * GBUF];     // 12.6 MB (Kh,Vh fp16)

// ---- helpers ----
__device__ __forceinline__ uint32_t smem_u32(const void* p) {
    uint32_t a;
    asm("{ .reg .u64 t; cvta.to.shared.u64 t, %1; cvt.u32.u64 %0, t; }" : "=r"(a) : "l"(p));
    return a;
}
__device__ __forceinline__ void cp_async16(uint32_t dst, const void* src) {
    asm volatile("cp.async.cg.shared.global [%0], [%1], 16;" :: "r"(dst), "l"(src));
}
#define CP_COMMIT() asm volatile("cp.async.commit_group;" ::: "memory")
#define CP_WAIT0()  asm volatile("cp.async.wait_group 0;" ::: "memory")

__device__ __forceinline__ void mma_f16(float* d, const uint32_t* a, uint32_t b0, uint32_t b1) {
    asm volatile(
        "mma.sync.aligned.m16n8k16.row.col.f32.f16.f16.f32 "
        "{%0,%1,%2,%3},{%4,%5,%6,%7},{%8,%9},{%0,%1,%2,%3};"
        : "+f"(d[0]), "+f"(d[1]), "+f"(d[2]), "+f"(d[3])
        : "r"(a[0]), "r"(a[1]), "r"(a[2]), "r"(a[3]), "r"(b0), "r"(b1));
}
__device__ __forceinline__ void ldsm_x4(uint32_t* r, uint32_t addr) {
    asm volatile("ldmatrix.sync.aligned.m8n8.x4.shared.b16 {%0,%1,%2,%3},[%4];"
                 : "=r"(r[0]), "=r"(r[1]), "=r"(r[2]), "=r"(r[3]) : "r"(addr));
}
__device__ __forceinline__ void ldsm_x4_t(uint32_t* r, uint32_t addr) {
    asm volatile("ldmatrix.sync.aligned.m8n8.x4.trans.shared.b16 {%0,%1,%2,%3},[%4];"
                 : "=r"(r[0]), "=r"(r[1]), "=r"(r[2]), "=r"(r[3]) : "r"(addr));
}
__device__ __forceinline__ uint32_t pack_h2(float a, float b) {
    uint32_t r;
    asm("cvt.rn.f16x2.f32 %0, %1, %2;" : "=r"(r) : "f"(b), "f"(a));
    return r;
}
__device__ __forceinline__ float ex2(float x) {
    float r;
    asm("ex2.approx.f32 %0, %1;" : "=f"(r) : "f"(x));
    return r;
}

// ---- merged prep: blocks [0, KVB) convert K/V; blocks [KVB, KVB+MB) pack mask ----
constexpr int KVB = Bc * Hc * NTILE;             // 1536 kv-tile blocks
constexpr int MB  = Bc * Sc * Sc / 8 / 256;      // 4096 mask blocks (8 ints/thread)

__global__ void __launch_bounds__(256) prep_kernel(
    const float* __restrict__ K, const float* __restrict__ V, const int4* __restrict__ m)
{
    const int t = threadIdx.x;
    if (blockIdx.x < KVB) {
        const int tile = blockIdx.x;
        const int bh = tile / NTILE, kt = tile % NTILE;
        const int k0 = kt * BN;
        uint32_t* out = g_kv + (size_t)tile * 2 * GBUF;
        const float4* K4 = reinterpret_cast<const float4*>(K) + (size_t)bh * Sc * 16;
        const float4* V4 = reinterpret_cast<const float4*>(V) + (size_t)bh * Sc * 16;
#pragma unroll
        for (int i = 0; i < 2; i++) {
            int idx = t + i * 256;
            int r = idx >> 4, c4 = idx & 15;
            int p0 = 2 * c4;
            float4 fk = K4[(size_t)(k0 + r) * 16 + c4];
            *reinterpret_cast<uint2*>(&out[0 * GBUF + r * 32 + p0]) =
                make_uint2(pack_h2(fk.x, fk.y), pack_h2(fk.z, fk.w));
            float4 fv = V4[(size_t)(k0 + r) * 16 + c4];
            *reinterpret_cast<uint2*>(&out[1 * GBUF + r * 32 + p0]) =
                make_uint2(pack_h2(fv.x, fv.y), pack_h2(fv.z, fv.w));
        }
    } else {
        size_t i = (size_t)(blockIdx.x - KVB) * 256 + t;   // 8-int chunk id
        int4 a = m[2 * i], c = m[2 * i + 1];
        uint32_t byte =
            (a.x != 0 ? 1u : 0u)  | (a.y != 0 ? 2u : 0u)  | (a.z != 0 ? 4u : 0u)  | (a.w != 0 ? 8u : 0u) |
            (c.x != 0 ? 16u : 0u) | (c.y != 0 ? 32u : 0u) | (c.z != 0 ? 64u : 0u) | (c.w != 0 ? 128u : 0u);
        uint32_t x = byte << (8 * (t & 3));
        x |= __shfl_xor_sync(0xFFFFFFFFu, x, 1);
        x |= __shfl_xor_sync(0xFFFFFFFFu, x, 2);
        if ((t & 3) == 0) g_mask_bits[i >> 2] = x;
    }
}

// ---- main attention kernel (software-pipelined S / PV) ----
__global__ void __launch_bounds__(NT, 2) attn_mma_kernel(
    const float* __restrict__ Q, float* __restrict__ Og)
{
    extern __shared__ uint32_t sTile[];         // NSTAGE x (Kh,Vh) x WBUF

    const int t = threadIdx.x;
    const int lane = t & 31, w = t >> 5;
    const int qt = lane >> 2, qc = lane & 3;

    const int q0 = blockIdx.x * BM;
    const int h = blockIdx.y, b = blockIdx.z;
    const size_t bh = (size_t)b * Hc + h;
    const int qi0 = q0 + w * 16 + qt;
    const int qi1 = qi0 + 8;

    // Q A-fragments (fp16), scale folded
    uint32_t qa[4][4];
#pragma unroll
    for (int kk = 0; kk < 4; kk++) {
#pragma unroll
        for (int part = 0; part < 4; part++) {
            int row = (part & 1) ? qi1 : qi0;
            int d = kk * 16 + 2 * qc + ((part & 2) ? 8 : 0);
            const float2 f = *reinterpret_cast<const float2*>(Q + ((bh * Sc + row) << 6) + d);
            qa[kk][part] = pack_h2(f.x * SCALE, f.y * SCALE);
        }
    }

    float oacc[8][4];
#pragma unroll
    for (int j = 0; j < 8; j++)
#pragma unroll
        for (int i = 0; i < 4; i++) oacc[j][i] = 0.0f;
    float lsum0 = 0.0f, lsum1 = 0.0f;

    const uint32_t* mrow0 = g_mask_bits + ((size_t)b * Sc + qi0) * (Sc / 32);
    const uint32_t* mrow1 = g_mask_bits + ((size_t)b * Sc + qi1) * (Sc / 32);
    const uint32_t* kvbase = g_kv + bh * NTILE * 2 * GBUF;
    const uint32_t sbase = smem_u32(sTile);

    auto issue_tile = [&](int kt, int stage) {
        const uint32_t* src = kvbase + (size_t)kt * 2 * GBUF;
        uint32_t dstb = sbase + (uint32_t)stage * 2 * WBUF * 4;
#pragma unroll
        for (int i = 0; i < 2; i++) {
            int chunk = t + i * NT;
            int buf = chunk >> 8, within = chunk & 255;
            int r = within >> 3, ws = within & 7;
            cp_async16(dstb + (uint32_t)(buf * WBUF + r * PITCHW + ws * 4) * 4,
                       src + buf * GBUF + within * 4);
        }
        CP_COMMIT();
    };

    // fragment address components
    const int krow = ((lane >> 4) << 3) + (lane & 7);
    const int ksel = (lane >> 3) & 1;
    const int vrow = ((lane >> 3) & 1) * 8 + (lane & 7);
    const int jsel = lane >> 4;

    float sacc[4][4];

    auto s_mma = [&](const uint32_t* sK) {
#pragma unroll
        for (int j = 0; j < 4; j++)
#pragma unroll
            for (int i = 0; i < 4; i++) sacc[j][i] = 0.0f;
#pragma unroll
        for (int jp = 0; jp < 2; jp++) {
            const int kr = jp * 16 + krow;
#pragma unroll
            for (int kk = 0; kk < 4; kk++) {
                uint32_t bh4[4];
                ldsm_x4(bh4, smem_u32(&sK[kr * PITCHW + kk * 8 + ksel * 4]));
                mma_f16(sacc[2 * jp],     qa[kk], bh4[0], bh4[1]);
                mma_f16(sacc[2 * jp + 1], qa[kk], bh4[2], bh4[3]);
            }
        }
    };

    uint32_t pa[2][4];

    auto softmax_pack = [&](int kt) {
        const uint32_t mw0 = mrow0[kt];
        const uint32_t mw1 = mrow1[kt];
#pragma unroll
        for (int j = 0; j < 4; j++) {
            const int sh = j * 8 + 2 * qc;
            float p0 = (mw0 >> sh) & 1       ? ex2(sacc[j][0] * LOG2E) : 0.0f;
            float p1 = (mw0 >> (sh + 1)) & 1 ? ex2(sacc[j][1] * LOG2E) : 0.0f;
            float p2 = (mw1 >> sh) & 1       ? ex2(sacc[j][2] * LOG2E) : 0.0f;
            float p3 = (mw1 >> (sh + 1)) & 1 ? ex2(sacc[j][3] * LOG2E) : 0.0f;
            lsum0 += p0 + p1;
            lsum1 += p2 + p3;
            pa[j >> 1][2 * (j & 1)]     = pack_h2(p0, p1);
            pa[j >> 1][2 * (j & 1) + 1] = pack_h2(p2, p3);
        }
    };

    auto pv_mma = [&](const uint32_t* sV) {
#pragma unroll
        for (int kc = 0; kc < 2; kc++) {
            const int vr = kc * 16 + vrow;
#pragma unroll
            for (int jp = 0; jp < 4; jp++) {
                uint32_t vh4[4];
                ldsm_x4_t(vh4, smem_u32(&sV[vr * PITCHW + (2 * jp + jsel) * 4]));
                mma_f16(oacc[2 * jp],     pa[kc], vh4[0], vh4[1]);
                mma_f16(oacc[2 * jp + 1], pa[kc], vh4[2], vh4[3]);
            }
        }
    };

    // ---- prologue: tiles 0,1 staged; S(0) computed ----
    issue_tile(0, 0);
    issue_tile(1, 1);
    CP_WAIT0();
    __syncthreads();
    s_mma(sTile /* stage 0 K */);

    // ---- pipelined loop: iter kt does exp(kt), PV(kt) || S(kt+1) ----
    for (int kt = 0; kt < NTILE - 1; kt++) {
        softmax_pack(kt);

        CP_WAIT0();            // tile kt+1 resident
        __syncthreads();       // all warps done with stage (kt-1)%3
        if (kt + 2 < NTILE) issue_tile(kt + 2, (kt + 2) % NSTAGE);   // lands in stage (kt-1)%3

        const uint32_t* sCur  = sTile + (kt % NSTAGE) * 2 * WBUF;        // V of tile kt
        const uint32_t* sNext = sTile + ((kt + 1) % NSTAGE) * 2 * WBUF;  // K of tile kt+1

        pv_mma(sCur + WBUF);   // independent of s_mma below -> interleaved by scheduler
        s_mma(sNext);
    }

    // ---- epilogue: last tile ----
    softmax_pack(NTILE - 1);
    pv_mma(sTile + ((NTILE - 1) % NSTAGE) * 2 * WBUF + WBUF);

    // ---- reduce row sums across quad, normalize, store ----
    lsum0 += __shfl_xor_sync(0xFFFFFFFFu, lsum0, 1);
    lsum0 += __shfl_xor_sync(0xFFFFFFFFu, lsum0, 2);
    lsum1 += __shfl_xor_sync(0xFFFFFFFFu, lsum1, 1);
    lsum1 += __shfl_xor_sync(0xFFFFFFFFu, lsum1, 2);
    const float inv0 = 1.0f / lsum0, inv1 = 1.0f / lsum1;

    float* o0 = Og + ((bh * Sc + qi0) << 6) + 2 * qc;
    float* o1 = Og + ((bh * Sc + qi1) << 6) + 2 * qc;
#pragma unroll
    for (int j = 0; j < 8; j++) {
        *reinterpret_cast<float2*>(o0 + j * 8) = make_float2(oacc[j][0] * inv0, oacc[j][1] * inv0);
        *reinterpret_cast<float2*>(o1 + j * 8) = make_float2(oacc[j][2] * inv1, oacc[j][3] * inv1);
    }
}

} // namespace

extern "C" void kernel_launch(void* const* d_in, const int* in_sizes, int n_in,
                              void* d_out, int out_size)
{
    const float* Q = (const float*)d_in[0];
    const float* K = (const float*)d_in[1];
    const float* V = (const float*)d_in[2];
    const int*   M = (const int*)d_in[3];
    float*       O = (float*)d_out;

    prep_kernel<<<KVB + MB, 256>>>(K, V, (const int4*)M);

    static int smem_set = 0;
    const int smem_bytes = NSTAGE * 2 * WBUF * 4;   // 27648
    if (!smem_set) {
        cudaFuncSetAttribute(attn_mma_kernel, cudaFuncAttributeMaxDynamicSharedMemorySize, smem_bytes);
        smem_set = 1;
    }
    dim3 grid(Sc / BM, Hc, Bc);
    attn_mma_kernel<<<grid, NT, smem_bytes>>>(Q, O);
}

// round 10
// speedup vs baseline: 1.1408x; 1.1175x over previous
#include <cuda_runtime.h>
#include <cuda_fp16.h>
#include <cstdint>

namespace {

constexpr int Bc = 2, Hc = 12, Sc = 2048, Dc = 64;
constexpr int BM = 128;          // q rows per CTA (16 per warp)
constexpr int BN = 32;           // keys per tile
constexpr int NT = 256;          // 8 warps
constexpr int NTILE = Sc / BN;   // 64
constexpr int NSTAGE = 3;
constexpr int PITCHW = 36;       // smem row pitch in words (144 B)
constexpr int WBUF = BN * PITCHW;
constexpr int GBUF = BN * 32;
constexpr int STAGE_BYTES = 2 * WBUF * 4;
// fold 1/sqrt(64) AND log2(e) into Q: S comes out of the MMA in log2 domain.
constexpr float QSCALE = 0.125f * 1.44269504f;
// M0 = 0: p = e^s stays fp16-normal (R5 failed on denormal quantization)

__device__ uint32_t g_mask_bits[(size_t)Bc * Sc * (Sc / 32)];     // 1 MB
__device__ uint32_t g_kv[(size_t)Bc * Hc * NTILE * 2 * GBUF];     // 12.6 MB (Kh,Vh fp16)

// ---- helpers ----
__device__ __forceinline__ uint32_t smem_u32(const void* p) {
    uint32_t a;
    asm("{ .reg .u64 t; cvta.to.shared.u64 t, %1; cvt.u32.u64 %0, t; }" : "=r"(a) : "l"(p));
    return a;
}
__device__ __forceinline__ void cp_async16(uint32_t dst, const void* src) {
    asm volatile("cp.async.cg.shared.global [%0], [%1], 16;" :: "r"(dst), "l"(src));
}
#define CP_COMMIT() asm volatile("cp.async.commit_group;" ::: "memory")
#define CP_WAIT0()  asm volatile("cp.async.wait_group 0;" ::: "memory")

__device__ __forceinline__ void mma_f16(float* d, const uint32_t* a, uint32_t b0, uint32_t b1) {
    asm volatile(
        "mma.sync.aligned.m16n8k16.row.col.f32.f16.f16.f32 "
        "{%0,%1,%2,%3},{%4,%5,%6,%7},{%8,%9},{%0,%1,%2,%3};"
        : "+f"(d[0]), "+f"(d[1]), "+f"(d[2]), "+f"(d[3])
        : "r"(a[0]), "r"(a[1]), "r"(a[2]), "r"(a[3]), "r"(b0), "r"(b1));
}
// d = a*b + 0  (no dependency on previous d; kills per-tile zero-init MOVs)
__device__ __forceinline__ void mma_f16_z(float* d, const uint32_t* a, uint32_t b0, uint32_t b1) {
    asm volatile(
        "mma.sync.aligned.m16n8k16.row.col.f32.f16.f16.f32 "
        "{%0,%1,%2,%3},{%4,%5,%6,%7},{%8,%9},{%10,%11,%12,%13};"
        : "=f"(d[0]), "=f"(d[1]), "=f"(d[2]), "=f"(d[3])
        : "r"(a[0]), "r"(a[1]), "r"(a[2]), "r"(a[3]), "r"(b0), "r"(b1),
          "f"(0.f), "f"(0.f), "f"(0.f), "f"(0.f));
}
__device__ __forceinline__ void ldsm_x4(uint32_t* r, uint32_t addr) {
    asm volatile("ldmatrix.sync.aligned.m8n8.x4.shared.b16 {%0,%1,%2,%3},[%4];"
                 : "=r"(r[0]), "=r"(r[1]), "=r"(r[2]), "=r"(r[3]) : "r"(addr));
}
__device__ __forceinline__ void ldsm_x4_t(uint32_t* r, uint32_t addr) {
    asm volatile("ldmatrix.sync.aligned.m8n8.x4.trans.shared.b16 {%0,%1,%2,%3},[%4];"
                 : "=r"(r[0]), "=r"(r[1]), "=r"(r[2]), "=r"(r[3]) : "r"(addr));
}
__device__ __forceinline__ uint32_t pack_h2(float a, float b) {
    uint32_t r;
    asm("cvt.rn.f16x2.f32 %0, %1, %2;" : "=r"(r) : "f"(b), "f"(a));
    return r;
}
__device__ __forceinline__ float ex2(float x) {
    float r;
    asm("ex2.approx.f32 %0, %1;" : "=f"(r) : "f"(x));
    return r;
}

// ---- merged prep: blocks [0, KVB) convert K/V; blocks [KVB, KVB+MB) pack mask ----
constexpr int KVB = Bc * Hc * NTILE;             // 1536
constexpr int MB  = Bc * Sc * Sc / 8 / 256;      // 4096

__global__ void __launch_bounds__(256) prep_kernel(
    const float* __restrict__ K, const float* __restrict__ V, const int4* __restrict__ m)
{
    const int t = threadIdx.x;
    if (blockIdx.x < KVB) {
        const int tile = blockIdx.x;
        const int bh = tile / NTILE, kt = tile % NTILE;
        const int k0 = kt * BN;
        uint32_t* out = g_kv + (size_t)tile * 2 * GBUF;
        const float4* K4 = reinterpret_cast<const float4*>(K) + (size_t)bh * Sc * 16;
        const float4* V4 = reinterpret_cast<const float4*>(V) + (size_t)bh * Sc * 16;
#pragma unroll
        for (int i = 0; i < 2; i++) {
            int idx = t + i * 256;
            int r = idx >> 4, c4 = idx & 15;
            int p0 = 2 * c4;
            float4 fk = K4[(size_t)(k0 + r) * 16 + c4];
            *reinterpret_cast<uint2*>(&out[0 * GBUF + r * 32 + p0]) =
                make_uint2(pack_h2(fk.x, fk.y), pack_h2(fk.z, fk.w));
            float4 fv = V4[(size_t)(k0 + r) * 16 + c4];
            *reinterpret_cast<uint2*>(&out[1 * GBUF + r * 32 + p0]) =
                make_uint2(pack_h2(fv.x, fv.y), pack_h2(fv.z, fv.w));
        }
    } else {
        size_t i = (size_t)(blockIdx.x - KVB) * 256 + t;
        int4 a = m[2 * i], c = m[2 * i + 1];
        uint32_t byte =
            (a.x != 0 ? 1u : 0u)  | (a.y != 0 ? 2u : 0u)  | (a.z != 0 ? 4u : 0u)  | (a.w != 0 ? 8u : 0u) |
            (c.x != 0 ? 16u : 0u) | (c.y != 0 ? 32u : 0u) | (c.z != 0 ? 64u : 0u) | (c.w != 0 ? 128u : 0u);
        uint32_t x = byte << (8 * (t & 3));
        x |= __shfl_xor_sync(0xFFFFFFFFu, x, 1);
        x |= __shfl_xor_sync(0xFFFFFFFFu, x, 2);
        if ((t & 3) == 0) g_mask_bits[i >> 2] = x;
    }
}

// ---- main attention kernel: 3x-unrolled pipeline, compile-time stages ----
__global__ void __launch_bounds__(NT, 2) attn_mma_kernel(
    const float* __restrict__ Q, float* __restrict__ Og)
{
    extern __shared__ uint32_t sTile[];

    const int t = threadIdx.x;
    const int lane = t & 31, w = t >> 5;
    const int qt = lane >> 2, qc = lane & 3;
    const int qs = 2 * qc;                        // mask pre-shift

    const int q0 = blockIdx.x * BM;
    const int h = blockIdx.y, b = blockIdx.z;
    const size_t bh = (size_t)b * Hc + h;
    const int qi0 = q0 + w * 16 + qt;
    const int qi1 = qi0 + 8;

    // Q A-fragments (fp16), scale*log2e folded
    uint32_t qa[4][4];
#pragma unroll
    for (int kk = 0; kk < 4; kk++) {
#pragma unroll
        for (int part = 0; part < 4; part++) {
            int row = (part & 1) ? qi1 : qi0;
            int d = kk * 16 + 2 * qc + ((part & 2) ? 8 : 0);
            const float2 f = *reinterpret_cast<const float2*>(Q + ((bh * Sc + row) << 6) + d);
            qa[kk][part] = pack_h2(f.x * QSCALE, f.y * QSCALE);
        }
    }

    float oacc[8][4];
#pragma unroll
    for (int j = 0; j < 8; j++)
#pragma unroll
        for (int i = 0; i < 4; i++) oacc[j][i] = 0.0f;
    float lsum0 = 0.0f, lsum1 = 0.0f;
    float sacc[4][4];
    uint32_t pa[2][4];
    uint32_t mwa, mwb;

    const uint32_t* mrow0 = g_mask_bits + ((size_t)b * Sc + qi0) * (Sc / 32);
    const uint32_t* mrow1 = g_mask_bits + ((size_t)b * Sc + qi1) * (Sc / 32);
    const uint32_t* kvsrc = g_kv + bh * NTILE * 2 * GBUF;
    const uint32_t sb = smem_u32(sTile);

    // ---- loop-invariant base addresses (stage offsets are compile-time imms) ----
    const int krow = ((lane >> 4) << 3) + (lane & 7);
    const int ksel = (lane >> 3) & 1;
    const int vrow = ((lane >> 3) & 1) * 8 + (lane & 7);
    const int jsel = lane >> 4;
    const uint32_t kb0 = sb + (uint32_t)(krow * PITCHW + ksel * 4) * 4;
    const uint32_t kb1 = kb0 + 16 * PITCHW * 4;
    const uint32_t vb  = sb + WBUF * 4 + (uint32_t)(vrow * PITCHW + jsel * 4) * 4;

    // cp.async per-thread dst offsets (chunk t and t+256)
    auto dstoff = [&](int chunk) {
        int buf = chunk >> 8, within = chunk & 255;
        int r = within >> 3, ws = within & 7;
        return (uint32_t)(buf * WBUF + r * PITCHW + ws * 4) * 4;
    };
    const uint32_t dst0 = sb + dstoff(t);
    const uint32_t dst1 = sb + dstoff(t + 256);

#define ISSUE(STG, ktv) do { \
    const uint32_t* _s = kvsrc + (size_t)(ktv) * (2 * GBUF); \
    cp_async16(dst0 + (STG) * STAGE_BYTES, _s + (t << 2)); \
    cp_async16(dst1 + (STG) * STAGE_BYTES, _s + ((t + 256) << 2)); \
    CP_COMMIT(); \
} while (0)

#define S_MMA(STG) do { \
    _Pragma("unroll") \
    for (int jp = 0; jp < 2; jp++) { \
        const uint32_t _kb = (jp ? kb1 : kb0) + (STG) * STAGE_BYTES; \
        { uint32_t f[4]; ldsm_x4(f, _kb); \
          mma_f16_z(sacc[2 * jp],     qa[0], f[0], f[1]); \
          mma_f16_z(sacc[2 * jp + 1], qa[0], f[2], f[3]); } \
        _Pragma("unroll") \
        for (int kk = 1; kk < 4; kk++) { \
            uint32_t f[4]; ldsm_x4(f, _kb + kk * 32); \
            mma_f16(sacc[2 * jp],     qa[kk], f[0], f[1]); \
            mma_f16(sacc[2 * jp + 1], qa[kk], f[2], f[3]); } \
    } \
} while (0)

#define SOFTMAX() do { \
    _Pragma("unroll") \
    for (int j = 0; j < 4; j++) { \
        const uint32_t _b0 = 1u << (8 * j), _b1 = 2u << (8 * j); \
        float p0 = (mwa & _b0) ? ex2(sacc[j][0]) : 0.0f; \
        float p1 = (mwa & _b1) ? ex2(sacc[j][1]) : 0.0f; \
        float p2 = (mwb & _b0) ? ex2(sacc[j][2]) : 0.0f; \
        float p3 = (mwb & _b1) ? ex2(sacc[j][3]) : 0.0f; \
        lsum0 += p0 + p1; \
        lsum1 += p2 + p3; \
        pa[j >> 1][2 * (j & 1)]     = pack_h2(p0, p1); \
        pa[j >> 1][2 * (j & 1) + 1] = pack_h2(p2, p3); \
    } \
} while (0)

#define PV_MMA(STG) do { \
    _Pragma("unroll") \
    for (int kc = 0; kc < 2; kc++) { \
        const uint32_t _vb = vb + (STG) * STAGE_BYTES + kc * (16 * PITCHW * 4); \
        _Pragma("unroll") \
        for (int jp = 0; jp < 4; jp++) { \
            uint32_t f[4]; ldsm_x4_t(f, _vb + jp * 32); \
            mma_f16(oacc[2 * jp],     pa[kc], f[0], f[1]); \
            mma_f16(oacc[2 * jp + 1], pa[kc], f[2], f[3]); } \
    } \
} while (0)

#define BODY(ktv, SC, SN, SL) do { \
    SOFTMAX(); \
    CP_WAIT0(); \
    __syncthreads(); \
    if ((ktv) + 2 < NTILE) ISSUE(SL, (ktv) + 2); \
    mwa = mrow0[(ktv) + 1] >> qs; \
    mwb = mrow1[(ktv) + 1] >> qs; \
    PV_MMA(SC); \
    S_MMA(SN); \
} while (0)

    // ---- prologue ----
    ISSUE(0, 0);
    ISSUE(1, 1);
    CP_WAIT0();
    __syncthreads();
    mwa = mrow0[0] >> qs;
    mwb = mrow1[0] >> qs;
    S_MMA(0);

    // ---- 21 x 3 pipelined bodies (kt = 0..62) ----
    for (int kt = 0; kt < NTILE - 1; kt += 3) {
        BODY(kt,     0, 1, 2);
        BODY(kt + 1, 1, 2, 0);
        BODY(kt + 2, 2, 0, 1);
    }

    // ---- epilogue: tile 63 (stage 0) ----
    SOFTMAX();
    PV_MMA(0);

#undef BODY
#undef PV_MMA
#undef SOFTMAX
#undef S_MMA
#undef ISSUE

    // ---- reduce row sums across quad, normalize, store ----
    lsum0 += __shfl_xor_sync(0xFFFFFFFFu, lsum0, 1);
    lsum0 += __shfl_xor_sync(0xFFFFFFFFu, lsum0, 2);
    lsum1 += __shfl_xor_sync(0xFFFFFFFFu, lsum1, 1);
    lsum1 += __shfl_xor_sync(0xFFFFFFFFu, lsum1, 2);
    const float inv0 = 1.0f / lsum0, inv1 = 1.0f / lsum1;

    float* o0 = Og + ((bh * Sc + qi0) << 6) + 2 * qc;
    float* o1 = Og + ((bh * Sc + qi1) << 6) + 2 * qc;
#pragma unroll
    for (int j = 0; j < 8; j++) {
        *reinterpret_cast<float2*>(o0 + j * 8) = make_float2(oacc[j][0] * inv0, oacc[j][1] * inv0);
        *reinterpret_cast<float2*>(o1 + j * 8) = make_float2(oacc[j][2] * inv1, oacc[j][3] * inv1);
    }
}

} // namespace

extern "C" void kernel_launch(void* const* d_in, const int* in_sizes, int n_in,
                              void* d_out, int out_size)
{
    const float* Q = (const float*)d_in[0];
    const float* K = (const float*)d_in[1];
    const float* V = (const float*)d_in[2];
    const int*   M = (const int*)d_in[3];
    float*       O = (float*)d_out;

    prep_kernel<<<KVB + MB, 256>>>(K, V, (const int4*)M);

    static int smem_set = 0;
    const int smem_bytes = NSTAGE * 2 * WBUF * 4;   // 27648
    if (!smem_set) {
        cudaFuncSetAttribute(attn_mma_kernel, cudaFuncAttributeMaxDynamicSharedMemorySize, smem_bytes);
        smem_set = 1;
    }
    dim3 grid(Sc / BM, Hc, Bc);
    attn_mma_kernel<<<grid, NT, smem_bytes>>>(Q, O);
}